// round 3
// baseline (speedup 1.0000x reference)
#include <cuda_runtime.h>
#include <cuda_bf16.h>
#include <math.h>

// Problem constants
#define BATCH   2
#define SEQLEN  1024
#define DMODEL  768
#define DINNER  1536
#define DSTATE  64
#define MROWS   (BATCH * SEQLEN)     // 2048
#define XDBL_LD 132

// Packed-K sizes (3x: [hi|lo|hi] for A-side, [hi|hi|lo] for B-side)
#define KP1 (3 * DMODEL)             // 2304, GEMM1 packed K
#define KP3 (3 * DINNER)             // 4608, GEMM3 packed K

// Scratch (device globals; no allocation allowed)
__device__ float g_xz   [MROWS * 2 * DINNER];
__device__ float g_xconv[MROWS * DINNER];
__device__ float g_xdbl [MROWS * XDBL_LD];
__device__ float g_pre  [MROWS * DINNER * 4];
__device__ __nv_bfloat16 g_xp [MROWS * KP1];        // x packed   [hi|lo|hi]
__device__ __nv_bfloat16 g_wip[2 * DINNER * KP1];   // W_in packed [hi|hi|lo]
__device__ __nv_bfloat16 g_y2 [MROWS * KP3];        // y packed   [hi|lo|hi]
__device__ __nv_bfloat16 g_wop[DMODEL * KP3];       // W_out packed [hi|hi|lo]

// ---------------------------------------------------------------------------
// Split-pack: fp32 [R,K] -> bf16 [R,3K].
// mode 0 (A-side): [hi | lo | hi]   mode 1 (B-side): [hi | hi | lo]
// ---------------------------------------------------------------------------
__global__ void split_pack(const float* __restrict__ in,
                           __nv_bfloat16* __restrict__ out,
                           int total4, int K4, int mode)
{
    int i = blockIdx.x * blockDim.x + threadIdx.x;
    if (i >= total4) return;
    int K = K4 * 4;
    int row = i / K4;
    int c4  = (i - row * K4) * 4;

    float4 v = *(const float4*)(in + (size_t)row * K + c4);
    float f[4] = {v.x, v.y, v.z, v.w};
    unsigned hi2[2], lo2[2];
#pragma unroll
    for (int t = 0; t < 2; t++) {
        __nv_bfloat16 h0 = __float2bfloat16_rn(f[2 * t]);
        __nv_bfloat16 h1 = __float2bfloat16_rn(f[2 * t + 1]);
        __nv_bfloat16 l0 = __float2bfloat16_rn(f[2 * t]     - __bfloat162float(h0));
        __nv_bfloat16 l1 = __float2bfloat16_rn(f[2 * t + 1] - __bfloat162float(h1));
        hi2[t] = (unsigned)__bfloat16_as_ushort(h0) |
                 ((unsigned)__bfloat16_as_ushort(h1) << 16);
        lo2[t] = (unsigned)__bfloat16_as_ushort(l0) |
                 ((unsigned)__bfloat16_as_ushort(l1) << 16);
    }
    uint2 hi = make_uint2(hi2[0], hi2[1]);
    uint2 lo = make_uint2(lo2[0], lo2[1]);

    __nv_bfloat16* base = out + (size_t)row * 3 * K + c4;
    *(uint2*)(base)         = hi;
    *(uint2*)(base + K)     = mode ? hi : lo;
    *(uint2*)(base + 2 * K) = mode ? lo : hi;
}

// ---------------------------------------------------------------------------
// Pipelined bf16 tensor-core GEMM: C[M,N] = A[M,K]*B[N,K]^T (fp32 out).
// BN=128, BK=32; BM template (128 or 64). cp.async double-buffered smem,
// padded 40-elem rows (conflict-free ldmatrix), m16n8k16 bf16 MMA.
// ---------------------------------------------------------------------------
__device__ __forceinline__ void mma16816(float* c, const unsigned* a,
                                         const unsigned* b)
{
    asm volatile(
        "mma.sync.aligned.m16n8k16.row.col.f32.bf16.bf16.f32 "
        "{%0,%1,%2,%3}, {%4,%5,%6,%7}, {%8,%9}, {%0,%1,%2,%3};\n"
        : "+f"(c[0]), "+f"(c[1]), "+f"(c[2]), "+f"(c[3])
        : "r"(a[0]), "r"(a[1]), "r"(a[2]), "r"(a[3]),
          "r"(b[0]), "r"(b[1]));
}

__device__ __forceinline__ void ldsm4(unsigned& r0, unsigned& r1,
                                      unsigned& r2, unsigned& r3,
                                      const void* p)
{
    unsigned a = (unsigned)__cvta_generic_to_shared(p);
    asm volatile("ldmatrix.sync.aligned.m8n8.x4.shared.b16 {%0,%1,%2,%3}, [%4];"
                 : "=r"(r0), "=r"(r1), "=r"(r2), "=r"(r3) : "r"(a));
}

__device__ __forceinline__ void cp16(void* smem, const void* gmem)
{
    unsigned s = (unsigned)__cvta_generic_to_shared(smem);
    asm volatile("cp.async.cg.shared.global [%0], [%1], 16;" :: "r"(s), "l"(gmem));
}

template<int BM>
__global__ __launch_bounds__(256) void gemm_bf16p(
    const __nv_bfloat16* __restrict__ A, const __nv_bfloat16* __restrict__ B,
    float* __restrict__ C, int M, int N, int K)
{
    constexpr int BN = 128, BK = 32;
    constexpr int WGM = (BM == 128) ? 2 : 1;
    constexpr int WGN = 8 / WGM;
    constexpr int MT = BM / (WGM * 16);   // 4
    constexpr int NT = BN / (WGN * 8);    // 4 or 2

    __shared__ __nv_bfloat16 As[2][BM][40];
    __shared__ __nv_bfloat16 Bs[2][BN][40];

    const int tid = threadIdx.x;
    const int lane = tid & 31;
    const int wid = tid >> 5;
    const int wm = wid % WGM;
    const int wn = wid / WGM;
    const int bm = blockIdx.y * BM;
    const int bn = blockIdx.x * BN;

    float c[MT][NT][4];
#pragma unroll
    for (int i = 0; i < MT; i++)
#pragma unroll
        for (int j = 0; j < NT; j++)
#pragma unroll
            for (int r = 0; r < 4; r++) c[i][j][r] = 0.f;

    auto load_stage = [&](int s, int k0) {
#pragma unroll
        for (int c0 = 0; c0 < BM * 4; c0 += 256) {
            int ci = c0 + tid;
            int row = ci >> 2, seg = ci & 3;
            cp16(&As[s][row][seg * 8],
                 A + (size_t)(bm + row) * K + k0 + seg * 8);
        }
#pragma unroll
        for (int c0 = 0; c0 < BN * 4; c0 += 256) {
            int ci = c0 + tid;
            int row = ci >> 2, seg = ci & 3;
            cp16(&Bs[s][row][seg * 8],
                 B + (size_t)(bn + row) * K + k0 + seg * 8);
        }
    };

    const int nIter = K / BK;
    load_stage(0, 0);
    asm volatile("cp.async.commit_group;");
    load_stage(1, BK);
    asm volatile("cp.async.commit_group;");
    asm volatile("cp.async.wait_group 1;");
    __syncthreads();

    for (int it = 0; it < nIter; it++) {
        const int s = it & 1;
#pragma unroll
        for (int ks = 0; ks < 2; ks++) {
            unsigned a[MT][4], b[NT][2];
#pragma unroll
            for (int i = 0; i < MT; i++) {
                ldsm4(a[i][0], a[i][1], a[i][2], a[i][3],
                      &As[s][wm * (MT * 16) + i * 16 + (lane & 15)]
                           [ks * 16 + ((lane >> 4) << 3)]);
            }
#pragma unroll
            for (int j2 = 0; j2 < NT / 2; j2++) {
                int r = wn * (NT * 8) + j2 * 16 + ((lane >> 4) << 3) + (lane & 7);
                int cb = (((lane >> 3) & 1) << 3) + ks * 16;
                ldsm4(b[2 * j2][0], b[2 * j2][1], b[2 * j2 + 1][0], b[2 * j2 + 1][1],
                      &Bs[s][r][cb]);
            }
#pragma unroll
            for (int i = 0; i < MT; i++)
#pragma unroll
                for (int j = 0; j < NT; j++)
                    mma16816(c[i][j], a[i], b[j]);
        }
        __syncthreads();                 // all warps done reading stage s
        if (it + 2 < nIter) load_stage(s, (it + 2) * BK);
        asm volatile("cp.async.commit_group;");
        asm volatile("cp.async.wait_group 1;");
        __syncthreads();                 // next stage's data ready
    }

#pragma unroll
    for (int i = 0; i < MT; i++) {
        int row = bm + wm * (MT * 16) + i * 16 + (lane >> 2);
#pragma unroll
        for (int j = 0; j < NT; j++) {
            int col = bn + wn * (NT * 8) + j * 8 + (lane & 3) * 2;
            *(float2*)(C + (size_t)row * N + col) =
                make_float2(c[i][j][0], c[i][j][1]);
            *(float2*)(C + (size_t)(row + 8) * N + col) =
                make_float2(c[i][j][2], c[i][j][3]);
        }
    }
}

// ---------------------------------------------------------------------------
// SGEMM 64x64x16 with N bounds + column remap (x_dbl). fp32.
// ---------------------------------------------------------------------------
__global__ __launch_bounds__(256) void sgemm64(
    const float* __restrict__ A, const float* __restrict__ B,
    float* __restrict__ C, int M, int N, int K, int ldc, int remap)
{
    __shared__ float As[16][68];
    __shared__ float Bs[16][68];

    const int tid = threadIdx.x;
    const int bm = blockIdx.y * 64;
    const int bn = blockIdx.x * 64;

    const int lr = tid >> 2;
    const int lk = (tid & 3) * 4;
    const int tx = tid & 15, ty = tid >> 4;

    float c[4][4];
#pragma unroll
    for (int i = 0; i < 4; i++)
#pragma unroll
        for (int j = 0; j < 4; j++) c[i][j] = 0.f;

    const float* Ag = A + (size_t)(bm + lr) * K + lk;
    const int brow = bn + lr;
    const float* Bg = B + (size_t)brow * K + lk;
    const bool bok = (brow < N);

    for (int k0 = 0; k0 < K; k0 += 16) {
        float4 av = *(const float4*)(Ag + k0);
        float4 bv = bok ? *(const float4*)(Bg + k0)
                        : make_float4(0.f, 0.f, 0.f, 0.f);
        As[lk + 0][lr] = av.x; As[lk + 1][lr] = av.y;
        As[lk + 2][lr] = av.z; As[lk + 3][lr] = av.w;
        Bs[lk + 0][lr] = bv.x; Bs[lk + 1][lr] = bv.y;
        Bs[lk + 2][lr] = bv.z; Bs[lk + 3][lr] = bv.w;
        __syncthreads();

#pragma unroll
        for (int k = 0; k < 16; k++) {
            float4 a = *(const float4*)&As[k][ty * 4];
            float4 b = *(const float4*)&Bs[k][tx * 4];
            float ar[4] = {a.x, a.y, a.z, a.w};
            float br[4] = {b.x, b.y, b.z, b.w};
#pragma unroll
            for (int i = 0; i < 4; i++)
#pragma unroll
                for (int j = 0; j < 4; j++)
                    c[i][j] = fmaf(ar[i], br[j], c[i][j]);
        }
        __syncthreads();
    }

#pragma unroll
    for (int i = 0; i < 4; i++) {
        int row = bm + ty * 4 + i;
#pragma unroll
        for (int j = 0; j < 4; j++) {
            int n = bn + tx * 4 + j;
            if (n < N) {
                int col = remap ? ((n == 0) ? 0 : n + 1) : n;
                C[(size_t)row * ldc + col] = c[i][j];
            }
        }
    }
}

// ---------------------------------------------------------------------------
// Causal conv (width 4) + SiLU
// ---------------------------------------------------------------------------
__global__ void conv_silu_kernel(const float* __restrict__ cw,
                                 const float* __restrict__ cb)
{
    int i = blockIdx.x * blockDim.x + threadIdx.x;
    const int ngrp = DINNER / 4;
    if (i >= MROWS * ngrp) return;
    int m  = i / ngrp;
    int dg = i % ngrp;
    int l  = m % SEQLEN;
    int d0 = dg * 4;

    float4 acc = make_float4(cb[d0], cb[d0 + 1], cb[d0 + 2], cb[d0 + 3]);
#pragma unroll
    for (int t = 0; t < 4; t++) {
        int li = l - 3 + t;
        if (li >= 0) {
            const float4 v = *(const float4*)&g_xz[(size_t)(m - l + li) * (2 * DINNER) + d0];
            acc.x = fmaf(v.x, __ldg(&cw[(d0 + 0) * 4 + t]), acc.x);
            acc.y = fmaf(v.y, __ldg(&cw[(d0 + 1) * 4 + t]), acc.y);
            acc.z = fmaf(v.z, __ldg(&cw[(d0 + 2) * 4 + t]), acc.z);
            acc.w = fmaf(v.w, __ldg(&cw[(d0 + 3) * 4 + t]), acc.w);
        }
    }
    float4 o;
    o.x = acc.x / (1.f + expf(-acc.x));
    o.y = acc.y / (1.f + expf(-acc.y));
    o.z = acc.z / (1.f + expf(-acc.z));
    o.w = acc.w / (1.f + expf(-acc.w));
    ((float4*)g_xconv)[i] = o;
}

// ---------------------------------------------------------------------------
// Precompute per-(m,d): {dt, dt*xc, D*xc*silu(z), silu(z)}
// ---------------------------------------------------------------------------
__global__ void pre_kernel(const float* __restrict__ dt_w,
                           const float* __restrict__ dt_b,
                           const float* __restrict__ Dp)
{
    int i = blockIdx.x * blockDim.x + threadIdx.x;
    if (i >= MROWS * DINNER) return;
    int m = i / DINNER, d = i % DINNER;

    float dtin = g_xdbl[(size_t)m * XDBL_LD];
    float xarg = fmaf(dtin, __ldg(&dt_w[d]), __ldg(&dt_b[d]));
    float dt = fmaxf(xarg, 0.f) + log1pf(expf(-fabsf(xarg)));

    float xc = g_xconv[i];
    float z  = g_xz[(size_t)m * (2 * DINNER) + DINNER + d];
    float sz = z / (1.f + expf(-z));

    float4 o = make_float4(dt, dt * xc, __ldg(&Dp[d]) * xc * sz, sz);
    ((float4*)g_pre)[i] = o;
}

// ---------------------------------------------------------------------------
// Selective scan: one warp per (b,d) channel; epilogue writes packed bf16 y.
// ---------------------------------------------------------------------------
__device__ __forceinline__ float fast_ex2(float x) {
    float r;
    asm("ex2.approx.ftz.f32 %0, %1;" : "=f"(r) : "f"(x));
    return r;
}

__global__ __launch_bounds__(256) void scan_kernel(const float* __restrict__ A_log)
{
    const int warp = threadIdx.x >> 5;
    const int lane = threadIdx.x & 31;
    const int ch = blockIdx.x * 8 + warp;
    const int b = ch / DINNER;
    const int d = ch % DINNER;
    const int n0 = 2 * lane;

    const float LOG2E = 1.4426950408889634f;
    const float An0 = -expf(A_log[n0])     * LOG2E;
    const float An1 = -expf(A_log[n0 + 1]) * LOG2E;

    const int mbase = b * SEQLEN;
    const float4* prp = (const float4*)g_pre + ((size_t)mbase * DINNER + d);
    const float*  xb  = g_xdbl + (size_t)mbase * XDBL_LD;
    __nv_bfloat16* yo = g_y2 + (size_t)mbase * KP3 + d;

    float h0 = 0.f, h1 = 0.f;
    float4 pr = __ldg(prp);
    float2 Bv = __ldg((const float2*)(xb + 2  + n0));
    float2 Cv = __ldg((const float2*)(xb + 66 + n0));

    for (int l = 0; l < SEQLEN; l++) {
        int ln = (l < SEQLEN - 1) ? (l + 1) : l;
        float4 prn = __ldg(prp + (size_t)ln * DINNER);
        float2 Bvn = __ldg((const float2*)(xb + (size_t)ln * XDBL_LD + 2  + n0));
        float2 Cvn = __ldg((const float2*)(xb + (size_t)ln * XDBL_LD + 66 + n0));

        float dA0 = fast_ex2(pr.x * An0);
        float dA1 = fast_ex2(pr.x * An1);
        h0 = fmaf(h0, dA0, Bv.x * pr.y);
        h1 = fmaf(h1, dA1, Bv.y * pr.y);
        float y = fmaf(h0, Cv.x, h1 * Cv.y);
#pragma unroll
        for (int o = 16; o > 0; o >>= 1)
            y += __shfl_xor_sync(0xffffffffu, y, o);
        if (lane == 0) {
            float yv = fmaf(y, pr.w, pr.z);
            __nv_bfloat16 hi = __float2bfloat16_rn(yv);
            __nv_bfloat16 lo = __float2bfloat16_rn(yv - __bfloat162float(hi));
            __nv_bfloat16* p = yo + (size_t)l * KP3;
            p[0]          = hi;
            p[DINNER]     = lo;
            p[2 * DINNER] = hi;
        }
        pr = prn; Bv = Bvn; Cv = Cvn;
    }
}

// ---------------------------------------------------------------------------
extern "C" void kernel_launch(void* const* d_in, const int* in_sizes, int n_in,
                              void* d_out, int out_size)
{
    const float* x      = (const float*)d_in[0];
    const float* W_in   = (const float*)d_in[1];
    const float* conv_w = (const float*)d_in[2];
    const float* conv_b = (const float*)d_in[3];
    const float* W_x    = (const float*)d_in[4];
    const float* dt_w   = (const float*)d_in[5];
    const float* dt_b   = (const float*)d_in[6];
    const float* A_log  = (const float*)d_in[7];
    const float* D_par  = (const float*)d_in[8];
    const float* W_out  = (const float*)d_in[9];
    float* out = (float*)d_out;

    float *p_xz, *p_xconv, *p_xdbl;
    __nv_bfloat16 *p_xp, *p_wip, *p_y2, *p_wop;
    cudaGetSymbolAddress((void**)&p_xz,    g_xz);
    cudaGetSymbolAddress((void**)&p_xconv, g_xconv);
    cudaGetSymbolAddress((void**)&p_xdbl,  g_xdbl);
    cudaGetSymbolAddress((void**)&p_xp,    g_xp);
    cudaGetSymbolAddress((void**)&p_wip,   g_wip);
    cudaGetSymbolAddress((void**)&p_y2,    g_y2);
    cudaGetSymbolAddress((void**)&p_wop,   g_wop);

    // 0) split-pack x, W_in, W_out into bf16 [hi|lo|hi] / [hi|hi|lo]
    {
        int t;
        t = MROWS * DMODEL / 4;
        split_pack<<<(t + 255) / 256, 256>>>(x, p_xp, t, DMODEL / 4, 0);
        t = 2 * DINNER * DMODEL / 4;
        split_pack<<<(t + 255) / 256, 256>>>(W_in, p_wip, t, DMODEL / 4, 1);
        t = DMODEL * DINNER / 4;
        split_pack<<<(t + 255) / 256, 256>>>(W_out, p_wop, t, DINNER / 4, 1);
    }

    // 1) xz = x @ W_in^T : [2048,3072]  (packed-K bf16 tensor GEMM)
    gemm_bf16p<128><<<dim3(2 * DINNER / 128, MROWS / 128), 256>>>(
        p_xp, p_wip, p_xz, MROWS, 2 * DINNER, KP1);

    // 2) causal conv + silu
    {
        int total = MROWS * (DINNER / 4);
        conv_silu_kernel<<<(total + 255) / 256, 256>>>(conv_w, conv_b);
    }

    // 3) x_dbl = x_conv @ W_x^T : [2048,129] -> g_xdbl (remapped cols)
    sgemm64<<<dim3((129 + 63) / 64, MROWS / 64), 256>>>(
        p_xconv, W_x, p_xdbl, MROWS, 129, DINNER, XDBL_LD, 1);

    // 4) precompute dt / dt*xc / D*xc*silu(z) / silu(z)
    {
        int total = MROWS * DINNER;
        pre_kernel<<<(total + 255) / 256, 256>>>(dt_w, dt_b, D_par);
    }

    // 5) selective scan -> g_y2 (packed bf16, gated + D folded)
    scan_kernel<<<(BATCH * DINNER) / 8, 256>>>(A_log);

    // 6) out = y @ W_out^T : [2048,768]  (packed-K bf16 tensor GEMM)
    gemm_bf16p<64><<<dim3(DMODEL / 128, MROWS / 64), 256>>>(
        p_y2, p_wop, out, MROWS, DMODEL, KP3);
}

// round 4
// speedup vs baseline: 1.0972x; 1.0972x over previous
#include <cuda_runtime.h>
#include <cuda_bf16.h>
#include <math.h>

// Problem constants
#define BATCH   2
#define SEQLEN  1024
#define DMODEL  768
#define DINNER  1536
#define DSTATE  64
#define MROWS   (BATCH * SEQLEN)     // 2048
#define XDBL_LD 132

// Packed-K sizes (3x: [hi|lo|hi] for A-side, [hi|hi|lo] for B-side)
#define KP1 (3 * DMODEL)             // 2304
#define KP3 (3 * DINNER)             // 4608

// Scratch (device globals; no allocation allowed)
__device__ float g_xz   [MROWS * 2 * DINNER];
__device__ float g_xconv[MROWS * DINNER];     // reused as split-K partials for GEMM3
__device__ float g_xdbl [MROWS * XDBL_LD];
__device__ float g_pre  [MROWS * DINNER * 4];
__device__ __nv_bfloat16 g_xp [MROWS * KP1];
__device__ __nv_bfloat16 g_wip[2 * DINNER * KP1];
__device__ __nv_bfloat16 g_y2 [MROWS * KP3];
__device__ __nv_bfloat16 g_wop[DMODEL * KP3];

// ---------------------------------------------------------------------------
// Split-pack: fp32 [R,K] -> bf16 [R,3K]. mode0: [hi|lo|hi]  mode1: [hi|hi|lo]
// ---------------------------------------------------------------------------
__global__ void split_pack(const float* __restrict__ in,
                           __nv_bfloat16* __restrict__ out,
                           int total4, int K4, int mode)
{
    int i = blockIdx.x * blockDim.x + threadIdx.x;
    if (i >= total4) return;
    int K = K4 * 4;
    int row = i / K4;
    int c4  = (i - row * K4) * 4;

    float4 v = *(const float4*)(in + (size_t)row * K + c4);
    float f[4] = {v.x, v.y, v.z, v.w};
    unsigned hi2[2], lo2[2];
#pragma unroll
    for (int t = 0; t < 2; t++) {
        __nv_bfloat16 h0 = __float2bfloat16_rn(f[2 * t]);
        __nv_bfloat16 h1 = __float2bfloat16_rn(f[2 * t + 1]);
        __nv_bfloat16 l0 = __float2bfloat16_rn(f[2 * t]     - __bfloat162float(h0));
        __nv_bfloat16 l1 = __float2bfloat16_rn(f[2 * t + 1] - __bfloat162float(h1));
        hi2[t] = (unsigned)__bfloat16_as_ushort(h0) |
                 ((unsigned)__bfloat16_as_ushort(h1) << 16);
        lo2[t] = (unsigned)__bfloat16_as_ushort(l0) |
                 ((unsigned)__bfloat16_as_ushort(l1) << 16);
    }
    uint2 hi = make_uint2(hi2[0], hi2[1]);
    uint2 lo = make_uint2(lo2[0], lo2[1]);

    __nv_bfloat16* base = out + (size_t)row * 3 * K + c4;
    *(uint2*)(base)         = hi;
    *(uint2*)(base + K)     = mode ? hi : lo;
    *(uint2*)(base + 2 * K) = mode ? lo : hi;
}

// ---------------------------------------------------------------------------
// 4-stage pipelined bf16 tensor-core GEMM: C[M,N] = A[M,kBase:kBase+kLen]*B^T
// 128x128x32 tiles, 8 warps (2x4), warp tile 64x32. One barrier per iter.
// gridDim.z = split-K slices; slice z writes C + z*M*N, uses kBase = z*kLen.
// ---------------------------------------------------------------------------
__device__ __forceinline__ void mma16816(float* c, const unsigned* a,
                                         const unsigned* b)
{
    asm volatile(
        "mma.sync.aligned.m16n8k16.row.col.f32.bf16.bf16.f32 "
        "{%0,%1,%2,%3}, {%4,%5,%6,%7}, {%8,%9}, {%0,%1,%2,%3};\n"
        : "+f"(c[0]), "+f"(c[1]), "+f"(c[2]), "+f"(c[3])
        : "r"(a[0]), "r"(a[1]), "r"(a[2]), "r"(a[3]),
          "r"(b[0]), "r"(b[1]));
}

__device__ __forceinline__ void ldsm4(unsigned& r0, unsigned& r1,
                                      unsigned& r2, unsigned& r3,
                                      const void* p)
{
    unsigned a = (unsigned)__cvta_generic_to_shared(p);
    asm volatile("ldmatrix.sync.aligned.m8n8.x4.shared.b16 {%0,%1,%2,%3}, [%4];"
                 : "=r"(r0), "=r"(r1), "=r"(r2), "=r"(r3) : "r"(a));
}

__device__ __forceinline__ void cp16(void* smem, const void* gmem)
{
    unsigned s = (unsigned)__cvta_generic_to_shared(smem);
    asm volatile("cp.async.cg.shared.global [%0], [%1], 16;" :: "r"(s), "l"(gmem));
}

#define NSTAGE 4

__global__ __launch_bounds__(256) void gemm_bf16p(
    const __nv_bfloat16* __restrict__ A, const __nv_bfloat16* __restrict__ B,
    float* __restrict__ C, int M, int N, int K, int kLen)
{
    constexpr int BM = 128, BN = 128, BK = 32;
    constexpr int MT = 4, NT = 4;

    __shared__ __nv_bfloat16 As[NSTAGE][BM][40];
    __shared__ __nv_bfloat16 Bs[NSTAGE][BN][40];

    const int tid  = threadIdx.x;
    const int lane = tid & 31;
    const int wid  = tid >> 5;
    const int wm   = wid & 1;
    const int wn   = wid >> 1;
    const int bm   = blockIdx.y * BM;
    const int bn   = blockIdx.x * BN;
    const int kBase = blockIdx.z * kLen;
    float* Cz = C + (size_t)blockIdx.z * M * N;

    // Per-thread staging coords: 2 rows each of A and B per stage
    const int srow = tid >> 2;          // 0..63
    const int sseg = tid & 3;           // 16B segment within 32-col slab
    const __nv_bfloat16* Ag = A + (size_t)(bm + srow) * K + kBase + sseg * 8;
    const __nv_bfloat16* Bg = B + (size_t)(bn + srow) * K + kBase + sseg * 8;

    float c[MT][NT][4];
#pragma unroll
    for (int i = 0; i < MT; i++)
#pragma unroll
        for (int j = 0; j < NT; j++)
#pragma unroll
            for (int r = 0; r < 4; r++) c[i][j][r] = 0.f;

    auto load_stage = [&](int s, int k0) {
        cp16(&As[s][srow][sseg * 8],      Ag + k0);
        cp16(&As[s][srow + 64][sseg * 8], Ag + (size_t)64 * K + k0);
        cp16(&Bs[s][srow][sseg * 8],      Bg + k0);
        cp16(&Bs[s][srow + 64][sseg * 8], Bg + (size_t)64 * K + k0);
    };

    auto compute_half = [&](int s, int ks) {
        unsigned a[MT][4], b[NT][2];
#pragma unroll
        for (int i = 0; i < MT; i++)
            ldsm4(a[i][0], a[i][1], a[i][2], a[i][3],
                  &As[s][wm * 64 + i * 16 + (lane & 15)]
                       [ks * 16 + ((lane >> 4) << 3)]);
#pragma unroll
        for (int j2 = 0; j2 < NT / 2; j2++) {
            int r = wn * 32 + j2 * 16 + ((lane >> 4) << 3) + (lane & 7);
            int cb = (((lane >> 3) & 1) << 3) + ks * 16;
            ldsm4(b[2 * j2][0], b[2 * j2][1], b[2 * j2 + 1][0], b[2 * j2 + 1][1],
                  &Bs[s][r][cb]);
        }
#pragma unroll
        for (int i = 0; i < MT; i++)
#pragma unroll
            for (int j = 0; j < NT; j++)
                mma16816(c[i][j], a[i], b[j]);
    };

    const int nIter = kLen / BK;

    // Prologue: fill NSTAGE-1 stages
#pragma unroll
    for (int p = 0; p < NSTAGE - 1; p++) {
        if (p < nIter) load_stage(p, p * BK);
        asm volatile("cp.async.commit_group;");
    }
    asm volatile("cp.async.wait_group %0;" :: "n"(NSTAGE - 2));
    __syncthreads();

    for (int it = 0; it < nIter; it++) {
        const int s = it & (NSTAGE - 1);
        compute_half(s, 0);
        {   // issue load for stage it+NSTAGE-1 (slot freed at end of prev iter)
            int nf = it + NSTAGE - 1;
            if (nf < nIter) load_stage(nf & (NSTAGE - 1), nf * BK);
            asm volatile("cp.async.commit_group;");
        }
        compute_half(s, 1);
        asm volatile("cp.async.wait_group %0;" :: "n"(NSTAGE - 2));
        __syncthreads();
    }

    // Epilogue
#pragma unroll
    for (int i = 0; i < MT; i++) {
        int row = bm + wm * 64 + i * 16 + (lane >> 2);
#pragma unroll
        for (int j = 0; j < NT; j++) {
            int col = bn + wn * 32 + j * 8 + (lane & 3) * 2;
            *(float2*)(Cz + (size_t)row * N + col) =
                make_float2(c[i][j][0], c[i][j][1]);
            *(float2*)(Cz + (size_t)(row + 8) * N + col) =
                make_float2(c[i][j][2], c[i][j][3]);
        }
    }
}

// Split-K reduction: out = p0 + p1 (float4 vectorized)
__global__ void addk_kernel(const float* __restrict__ p, float* __restrict__ out,
                            int total4)
{
    int i = blockIdx.x * blockDim.x + threadIdx.x;
    if (i >= total4) return;
    float4 a = ((const float4*)p)[i];
    float4 b = ((const float4*)p)[i + total4];
    ((float4*)out)[i] = make_float4(a.x + b.x, a.y + b.y, a.z + b.z, a.w + b.w);
}

// ---------------------------------------------------------------------------
// SGEMM 64x64x16 with N bounds + column remap (x_dbl). fp32.
// ---------------------------------------------------------------------------
__global__ __launch_bounds__(256) void sgemm64(
    const float* __restrict__ A, const float* __restrict__ B,
    float* __restrict__ C, int M, int N, int K, int ldc, int remap)
{
    __shared__ float As[16][68];
    __shared__ float Bs[16][68];

    const int tid = threadIdx.x;
    const int bm = blockIdx.y * 64;
    const int bn = blockIdx.x * 64;

    const int lr = tid >> 2;
    const int lk = (tid & 3) * 4;
    const int tx = tid & 15, ty = tid >> 4;

    float c[4][4];
#pragma unroll
    for (int i = 0; i < 4; i++)
#pragma unroll
        for (int j = 0; j < 4; j++) c[i][j] = 0.f;

    const float* Ag = A + (size_t)(bm + lr) * K + lk;
    const int brow = bn + lr;
    const float* Bg = B + (size_t)brow * K + lk;
    const bool bok = (brow < N);

    for (int k0 = 0; k0 < K; k0 += 16) {
        float4 av = *(const float4*)(Ag + k0);
        float4 bv = bok ? *(const float4*)(Bg + k0)
                        : make_float4(0.f, 0.f, 0.f, 0.f);
        As[lk + 0][lr] = av.x; As[lk + 1][lr] = av.y;
        As[lk + 2][lr] = av.z; As[lk + 3][lr] = av.w;
        Bs[lk + 0][lr] = bv.x; Bs[lk + 1][lr] = bv.y;
        Bs[lk + 2][lr] = bv.z; Bs[lk + 3][lr] = bv.w;
        __syncthreads();

#pragma unroll
        for (int k = 0; k < 16; k++) {
            float4 a = *(const float4*)&As[k][ty * 4];
            float4 b = *(const float4*)&Bs[k][tx * 4];
            float ar[4] = {a.x, a.y, a.z, a.w};
            float br[4] = {b.x, b.y, b.z, b.w};
#pragma unroll
            for (int i = 0; i < 4; i++)
#pragma unroll
                for (int j = 0; j < 4; j++)
                    c[i][j] = fmaf(ar[i], br[j], c[i][j]);
        }
        __syncthreads();
    }

#pragma unroll
    for (int i = 0; i < 4; i++) {
        int row = bm + ty * 4 + i;
#pragma unroll
        for (int j = 0; j < 4; j++) {
            int n = bn + tx * 4 + j;
            if (n < N) {
                int col = remap ? ((n == 0) ? 0 : n + 1) : n;
                C[(size_t)row * ldc + col] = c[i][j];
            }
        }
    }
}

// ---------------------------------------------------------------------------
// Causal conv (width 4) + SiLU -> g_xz z-half untouched; writes g_xconv... but
// g_xconv is reused later; conv output stored in its own region (first pass).
// ---------------------------------------------------------------------------
__device__ float g_xc2[MROWS * DINNER];   // conv output (separate from partials)

__global__ void conv_silu_kernel(const float* __restrict__ cw,
                                 const float* __restrict__ cb)
{
    int i = blockIdx.x * blockDim.x + threadIdx.x;
    const int ngrp = DINNER / 4;
    if (i >= MROWS * ngrp) return;
    int m  = i / ngrp;
    int dg = i % ngrp;
    int l  = m % SEQLEN;
    int d0 = dg * 4;

    float4 acc = make_float4(cb[d0], cb[d0 + 1], cb[d0 + 2], cb[d0 + 3]);
#pragma unroll
    for (int t = 0; t < 4; t++) {
        int li = l - 3 + t;
        if (li >= 0) {
            const float4 v = *(const float4*)&g_xz[(size_t)(m - l + li) * (2 * DINNER) + d0];
            acc.x = fmaf(v.x, __ldg(&cw[(d0 + 0) * 4 + t]), acc.x);
            acc.y = fmaf(v.y, __ldg(&cw[(d0 + 1) * 4 + t]), acc.y);
            acc.z = fmaf(v.z, __ldg(&cw[(d0 + 2) * 4 + t]), acc.z);
            acc.w = fmaf(v.w, __ldg(&cw[(d0 + 3) * 4 + t]), acc.w);
        }
    }
    float4 o;
    o.x = acc.x / (1.f + expf(-acc.x));
    o.y = acc.y / (1.f + expf(-acc.y));
    o.z = acc.z / (1.f + expf(-acc.z));
    o.w = acc.w / (1.f + expf(-acc.w));
    ((float4*)g_xc2)[i] = o;
}

// ---------------------------------------------------------------------------
// Precompute per-(m,d): {dt, dt*xc, D*xc*silu(z), silu(z)}
// ---------------------------------------------------------------------------
__global__ void pre_kernel(const float* __restrict__ dt_w,
                           const float* __restrict__ dt_b,
                           const float* __restrict__ Dp)
{
    int i = blockIdx.x * blockDim.x + threadIdx.x;
    if (i >= MROWS * DINNER) return;
    int m = i / DINNER, d = i % DINNER;

    float dtin = g_xdbl[(size_t)m * XDBL_LD];
    float xarg = fmaf(dtin, __ldg(&dt_w[d]), __ldg(&dt_b[d]));
    float dt = fmaxf(xarg, 0.f) + log1pf(expf(-fabsf(xarg)));

    float xc = g_xc2[i];
    float z  = g_xz[(size_t)m * (2 * DINNER) + DINNER + d];
    float sz = z / (1.f + expf(-z));

    float4 o = make_float4(dt, dt * xc, __ldg(&Dp[d]) * xc * sz, sz);
    ((float4*)g_pre)[i] = o;
}

// ---------------------------------------------------------------------------
// Selective scan: one warp per (b,d) channel; writes packed bf16 y directly.
// ---------------------------------------------------------------------------
__device__ __forceinline__ float fast_ex2(float x) {
    float r;
    asm("ex2.approx.ftz.f32 %0, %1;" : "=f"(r) : "f"(x));
    return r;
}

__global__ __launch_bounds__(256) void scan_kernel(const float* __restrict__ A_log)
{
    const int warp = threadIdx.x >> 5;
    const int lane = threadIdx.x & 31;
    const int ch = blockIdx.x * 8 + warp;
    const int b = ch / DINNER;
    const int d = ch % DINNER;
    const int n0 = 2 * lane;

    const float LOG2E = 1.4426950408889634f;
    const float An0 = -expf(A_log[n0])     * LOG2E;
    const float An1 = -expf(A_log[n0 + 1]) * LOG2E;

    const int mbase = b * SEQLEN;
    const float4* prp = (const float4*)g_pre + ((size_t)mbase * DINNER + d);
    const float*  xb  = g_xdbl + (size_t)mbase * XDBL_LD;
    __nv_bfloat16* yo = g_y2 + (size_t)mbase * KP3 + d;

    float h0 = 0.f, h1 = 0.f;
    float4 pr = __ldg(prp);
    float2 Bv = __ldg((const float2*)(xb + 2  + n0));
    float2 Cv = __ldg((const float2*)(xb + 66 + n0));

    for (int l = 0; l < SEQLEN; l++) {
        int ln = (l < SEQLEN - 1) ? (l + 1) : l;
        float4 prn = __ldg(prp + (size_t)ln * DINNER);
        float2 Bvn = __ldg((const float2*)(xb + (size_t)ln * XDBL_LD + 2  + n0));
        float2 Cvn = __ldg((const float2*)(xb + (size_t)ln * XDBL_LD + 66 + n0));

        float dA0 = fast_ex2(pr.x * An0);
        float dA1 = fast_ex2(pr.x * An1);
        h0 = fmaf(h0, dA0, Bv.x * pr.y);
        h1 = fmaf(h1, dA1, Bv.y * pr.y);
        float y = fmaf(h0, Cv.x, h1 * Cv.y);
#pragma unroll
        for (int o = 16; o > 0; o >>= 1)
            y += __shfl_xor_sync(0xffffffffu, y, o);
        if (lane == 0) {
            float yv = fmaf(y, pr.w, pr.z);
            __nv_bfloat16 hi = __float2bfloat16_rn(yv);
            __nv_bfloat16 lo = __float2bfloat16_rn(yv - __bfloat162float(hi));
            __nv_bfloat16* p = yo + (size_t)l * KP3;
            p[0]          = hi;
            p[DINNER]     = lo;
            p[2 * DINNER] = hi;
        }
        pr = prn; Bv = Bvn; Cv = Cvn;
    }
}

// ---------------------------------------------------------------------------
extern "C" void kernel_launch(void* const* d_in, const int* in_sizes, int n_in,
                              void* d_out, int out_size)
{
    const float* x      = (const float*)d_in[0];
    const float* W_in   = (const float*)d_in[1];
    const float* conv_w = (const float*)d_in[2];
    const float* conv_b = (const float*)d_in[3];
    const float* W_x    = (const float*)d_in[4];
    const float* dt_w   = (const float*)d_in[5];
    const float* dt_b   = (const float*)d_in[6];
    const float* A_log  = (const float*)d_in[7];
    const float* D_par  = (const float*)d_in[8];
    const float* W_out  = (const float*)d_in[9];
    float* out = (float*)d_out;

    float *p_xz, *p_xc2, *p_xdbl, *p_part;
    __nv_bfloat16 *p_xp, *p_wip, *p_y2, *p_wop;
    cudaGetSymbolAddress((void**)&p_xz,    g_xz);
    cudaGetSymbolAddress((void**)&p_xc2,   g_xc2);
    cudaGetSymbolAddress((void**)&p_xdbl,  g_xdbl);
    cudaGetSymbolAddress((void**)&p_part,  g_xconv);   // split-K partials
    cudaGetSymbolAddress((void**)&p_xp,    g_xp);
    cudaGetSymbolAddress((void**)&p_wip,   g_wip);
    cudaGetSymbolAddress((void**)&p_y2,    g_y2);
    cudaGetSymbolAddress((void**)&p_wop,   g_wop);

    // 0) split-pack x, W_in, W_out
    {
        int t;
        t = MROWS * DMODEL / 4;
        split_pack<<<(t + 255) / 256, 256>>>(x, p_xp, t, DMODEL / 4, 0);
        t = 2 * DINNER * DMODEL / 4;
        split_pack<<<(t + 255) / 256, 256>>>(W_in, p_wip, t, DMODEL / 4, 1);
        t = DMODEL * DINNER / 4;
        split_pack<<<(t + 255) / 256, 256>>>(W_out, p_wop, t, DINNER / 4, 1);
    }

    // 1) xz = x @ W_in^T : [2048,3072]
    gemm_bf16p<<<dim3(2 * DINNER / 128, MROWS / 128, 1), 256>>>(
        p_xp, p_wip, p_xz, MROWS, 2 * DINNER, KP1, KP1);

    // 2) causal conv + silu
    {
        int total = MROWS * (DINNER / 4);
        conv_silu_kernel<<<(total + 255) / 256, 256>>>(conv_w, conv_b);
    }

    // 3) x_dbl = x_conv @ W_x^T : [2048,129] (remapped cols)
    sgemm64<<<dim3((129 + 63) / 64, MROWS / 64), 256>>>(
        p_xc2, W_x, p_xdbl, MROWS, 129, DINNER, XDBL_LD, 1);

    // 4) precompute {dt, dt*xc, D*xc*sz, sz}
    {
        int total = MROWS * DINNER;
        pre_kernel<<<(total + 255) / 256, 256>>>(dt_w, dt_b, D_par);
    }

    // 5) selective scan -> g_y2 (packed bf16)
    scan_kernel<<<(BATCH * DINNER) / 8, 256>>>(A_log);

    // 6) out = y @ W_out^T : [2048,768], split-K=2 into partials, then add
    gemm_bf16p<<<dim3(DMODEL / 128, MROWS / 128, 2), 256>>>(
        p_y2, p_wop, p_part, MROWS, DMODEL, KP3, KP3 / 2);
    {
        int t4 = MROWS * DMODEL / 4;
        addk_kernel<<<(t4 + 255) / 256, 256>>>(p_part, out, t4);
    }
}

// round 5
// speedup vs baseline: 1.5428x; 1.4061x over previous
#include <cuda_runtime.h>
#include <cuda_bf16.h>
#include <math.h>

#define BATCH   2
#define SEQLEN  1024
#define DMODEL  768
#define DINNER  1536
#define DSTATE  64
#define MROWS   (BATCH * SEQLEN)
#define XDBL_LD 132

#define KP1 (3 * DMODEL)             // 2304
#define KP3 (3 * DINNER)             // 4608

// Scratch
__device__ float g_xz   [MROWS * 2 * DINNER];
__device__ float g_xconv[MROWS * DINNER];       // sgemm64 split-K partials
__device__ float g_xc2  [MROWS * DINNER];       // conv output
__device__ float g_xdbl [MROWS * XDBL_LD];
__device__ float g_pre  [MROWS * DINNER * 4];   // pre (ch-major) / GEMM3 partials
__device__ __nv_bfloat16 g_xp [MROWS * KP1];
__device__ __nv_bfloat16 g_wip[2 * DINNER * KP1];
__device__ __nv_bfloat16 g_y2 [MROWS * KP3];    // y packed interleaved [hi,lo,hi] per d
__device__ __nv_bfloat16 g_wop[DMODEL * KP3];   // W_out packed interleaved [hi,hi,lo]

// ---------------------------------------------------------------------------
// Split-pack fp32 [R,K] -> bf16 [R,3K].
// mode0: blocks [hi|lo|hi]; mode1: blocks [hi|hi|lo]; mode2: interleaved
// per-element [hi,hi,lo] at 3k (for GEMM3 B side).
// ---------------------------------------------------------------------------
__global__ void split_pack(const float* __restrict__ in,
                           __nv_bfloat16* __restrict__ out,
                           int total4, int K4, int mode)
{
    int i = blockIdx.x * blockDim.x + threadIdx.x;
    if (i >= total4) return;
    int K = K4 * 4;
    int row = i / K4;
    int c4  = (i - row * K4) * 4;

    float4 v = *(const float4*)(in + (size_t)row * K + c4);
    float f[4] = {v.x, v.y, v.z, v.w};
    unsigned hs[4], ls[4];
#pragma unroll
    for (int t = 0; t < 4; t++) {
        __nv_bfloat16 h = __float2bfloat16_rn(f[t]);
        __nv_bfloat16 l = __float2bfloat16_rn(f[t] - __bfloat162float(h));
        hs[t] = (unsigned)__bfloat16_as_ushort(h);
        ls[t] = (unsigned)__bfloat16_as_ushort(l);
    }

    if (mode == 2) {
        // interleaved: per element k -> [hi,hi,lo] at 3k; 4 elems = 24B
        unsigned w0 = hs[0] | (hs[0] << 16);
        unsigned w1 = ls[0] | (hs[1] << 16);
        unsigned w2 = hs[1] | (ls[1] << 16);
        unsigned w3 = hs[2] | (hs[2] << 16);
        unsigned w4 = ls[2] | (hs[3] << 16);
        unsigned w5 = hs[3] | (ls[3] << 16);
        uint2* wp = (uint2*)(out + (size_t)row * 3 * K + 3 * c4);
        wp[0] = make_uint2(w0, w1);
        wp[1] = make_uint2(w2, w3);
        wp[2] = make_uint2(w4, w5);
    } else {
        uint2 hi = make_uint2(hs[0] | (hs[1] << 16), hs[2] | (hs[3] << 16));
        uint2 lo = make_uint2(ls[0] | (ls[1] << 16), ls[2] | (ls[3] << 16));
        __nv_bfloat16* base = out + (size_t)row * 3 * K + c4;
        *(uint2*)(base)         = hi;
        *(uint2*)(base + K)     = mode ? hi : lo;
        *(uint2*)(base + 2 * K) = mode ? lo : hi;
    }
}

// ---------------------------------------------------------------------------
// 3-stage pipelined bf16 tensor GEMM, 128x128x32, launch_bounds(256,2).
// gridDim.z = split-K slices (slice z: kBase=z*kLen, writes C+z*M*N).
// ---------------------------------------------------------------------------
__device__ __forceinline__ void mma16816(float* c, const unsigned* a,
                                         const unsigned* b)
{
    asm volatile(
        "mma.sync.aligned.m16n8k16.row.col.f32.bf16.bf16.f32 "
        "{%0,%1,%2,%3}, {%4,%5,%6,%7}, {%8,%9}, {%0,%1,%2,%3};\n"
        : "+f"(c[0]), "+f"(c[1]), "+f"(c[2]), "+f"(c[3])
        : "r"(a[0]), "r"(a[1]), "r"(a[2]), "r"(a[3]),
          "r"(b[0]), "r"(b[1]));
}

__device__ __forceinline__ void ldsm4(unsigned& r0, unsigned& r1,
                                      unsigned& r2, unsigned& r3,
                                      const void* p)
{
    unsigned a = (unsigned)__cvta_generic_to_shared(p);
    asm volatile("ldmatrix.sync.aligned.m8n8.x4.shared.b16 {%0,%1,%2,%3}, [%4];"
                 : "=r"(r0), "=r"(r1), "=r"(r2), "=r"(r3) : "r"(a));
}

__device__ __forceinline__ void cp16(void* smem, const void* gmem)
{
    unsigned s = (unsigned)__cvta_generic_to_shared(smem);
    asm volatile("cp.async.cg.shared.global [%0], [%1], 16;" :: "r"(s), "l"(gmem));
}

#define NSTAGE 3

__global__ __launch_bounds__(256, 2) void gemm_bf16p(
    const __nv_bfloat16* __restrict__ A, const __nv_bfloat16* __restrict__ B,
    float* __restrict__ C, int M, int N, int K, int kLen)
{
    constexpr int BM = 128, BN = 128, BK = 32;
    constexpr int MT = 4, NT = 4;

    __shared__ __nv_bfloat16 As[NSTAGE][BM][40];
    __shared__ __nv_bfloat16 Bs[NSTAGE][BN][40];

    const int tid  = threadIdx.x;
    const int lane = tid & 31;
    const int wid  = tid >> 5;
    const int wm   = wid & 1;
    const int wn   = wid >> 1;
    const int bm   = blockIdx.y * BM;
    const int bn   = blockIdx.x * BN;
    const int kBase = blockIdx.z * kLen;
    float* Cz = C + (size_t)blockIdx.z * M * N;

    const int srow = tid >> 2;
    const int sseg = tid & 3;
    const __nv_bfloat16* Ag = A + (size_t)(bm + srow) * K + kBase + sseg * 8;
    const __nv_bfloat16* Bg = B + (size_t)(bn + srow) * K + kBase + sseg * 8;

    float c[MT][NT][4];
#pragma unroll
    for (int i = 0; i < MT; i++)
#pragma unroll
        for (int j = 0; j < NT; j++)
#pragma unroll
            for (int r = 0; r < 4; r++) c[i][j][r] = 0.f;

    auto load_stage = [&](int s, int k0) {
        cp16(&As[s][srow][sseg * 8],      Ag + k0);
        cp16(&As[s][srow + 64][sseg * 8], Ag + (size_t)64 * K + k0);
        cp16(&Bs[s][srow][sseg * 8],      Bg + k0);
        cp16(&Bs[s][srow + 64][sseg * 8], Bg + (size_t)64 * K + k0);
    };

    auto compute_half = [&](int s, int ks) {
        unsigned a[MT][4], b[NT][2];
#pragma unroll
        for (int i = 0; i < MT; i++)
            ldsm4(a[i][0], a[i][1], a[i][2], a[i][3],
                  &As[s][wm * 64 + i * 16 + (lane & 15)]
                       [ks * 16 + ((lane >> 4) << 3)]);
#pragma unroll
        for (int j2 = 0; j2 < NT / 2; j2++) {
            int r = wn * 32 + j2 * 16 + ((lane >> 4) << 3) + (lane & 7);
            int cb = (((lane >> 3) & 1) << 3) + ks * 16;
            ldsm4(b[2 * j2][0], b[2 * j2][1], b[2 * j2 + 1][0], b[2 * j2 + 1][1],
                  &Bs[s][r][cb]);
        }
#pragma unroll
        for (int i = 0; i < MT; i++)
#pragma unroll
            for (int j = 0; j < NT; j++)
                mma16816(c[i][j], a[i], b[j]);
    };

    const int nIter = kLen / BK;

    load_stage(0, 0);
    asm volatile("cp.async.commit_group;");
    if (1 < nIter) load_stage(1, BK);
    asm volatile("cp.async.commit_group;");
    asm volatile("cp.async.wait_group 1;");
    __syncthreads();

    int s = 0;
    for (int it = 0; it < nIter; it++) {
        compute_half(s, 0);
        {
            int nf = it + 2;
            int sl = s + 2; if (sl >= NSTAGE) sl -= NSTAGE;
            if (nf < nIter) load_stage(sl, nf * BK);
            asm volatile("cp.async.commit_group;");
        }
        compute_half(s, 1);
        asm volatile("cp.async.wait_group 1;");
        __syncthreads();
        s = (s + 1 == NSTAGE) ? 0 : s + 1;
    }

#pragma unroll
    for (int i = 0; i < MT; i++) {
        int row = bm + wm * 64 + i * 16 + (lane >> 2);
#pragma unroll
        for (int j = 0; j < NT; j++) {
            int col = bn + wn * 32 + j * 8 + (lane & 3) * 2;
            *(float2*)(Cz + (size_t)row * N + col) =
                make_float2(c[i][j][0], c[i][j][1]);
            *(float2*)(Cz + (size_t)(row + 8) * N + col) =
                make_float2(c[i][j][2], c[i][j][3]);
        }
    }
}

// Split-K reduction: out = sum of ns slices
__global__ void addk_kernel(const float* __restrict__ p, float* __restrict__ out,
                            int total4, int ns)
{
    int i = blockIdx.x * blockDim.x + threadIdx.x;
    if (i >= total4) return;
    float4 a = ((const float4*)p)[i];
    for (int s = 1; s < ns; s++) {
        float4 b = ((const float4*)p)[i + (size_t)s * total4];
        a.x += b.x; a.y += b.y; a.z += b.z; a.w += b.w;
    }
    ((float4*)out)[i] = a;
}

// ---------------------------------------------------------------------------
// SGEMM 64x64x16, fp32, N bounds + remap; split-K via gridDim.z.
// ---------------------------------------------------------------------------
__global__ __launch_bounds__(256) void sgemm64(
    const float* __restrict__ A, const float* __restrict__ B,
    float* __restrict__ C, int M, int N, int K, int ldc, int remap, int kLen)
{
    __shared__ float As[16][68];
    __shared__ float Bs[16][68];

    const int tid = threadIdx.x;
    const int bm = blockIdx.y * 64;
    const int bn = blockIdx.x * 64;
    const int kBase = blockIdx.z * kLen;
    float* Cz = C + (size_t)blockIdx.z * M * ldc;

    const int lr = tid >> 2;
    const int lk = (tid & 3) * 4;
    const int tx = tid & 15, ty = tid >> 4;

    float c[4][4];
#pragma unroll
    for (int i = 0; i < 4; i++)
#pragma unroll
        for (int j = 0; j < 4; j++) c[i][j] = 0.f;

    const float* Ag = A + (size_t)(bm + lr) * K + kBase + lk;
    const int brow = bn + lr;
    const float* Bg = B + (size_t)brow * K + kBase + lk;
    const bool bok = (brow < N);

    for (int k0 = 0; k0 < kLen; k0 += 16) {
        float4 av = *(const float4*)(Ag + k0);
        float4 bv = bok ? *(const float4*)(Bg + k0)
                        : make_float4(0.f, 0.f, 0.f, 0.f);
        As[lk + 0][lr] = av.x; As[lk + 1][lr] = av.y;
        As[lk + 2][lr] = av.z; As[lk + 3][lr] = av.w;
        Bs[lk + 0][lr] = bv.x; Bs[lk + 1][lr] = bv.y;
        Bs[lk + 2][lr] = bv.z; Bs[lk + 3][lr] = bv.w;
        __syncthreads();

#pragma unroll
        for (int k = 0; k < 16; k++) {
            float4 a = *(const float4*)&As[k][ty * 4];
            float4 b = *(const float4*)&Bs[k][tx * 4];
            float ar[4] = {a.x, a.y, a.z, a.w};
            float br[4] = {b.x, b.y, b.z, b.w};
#pragma unroll
            for (int i = 0; i < 4; i++)
#pragma unroll
                for (int j = 0; j < 4; j++)
                    c[i][j] = fmaf(ar[i], br[j], c[i][j]);
        }
        __syncthreads();
    }

#pragma unroll
    for (int i = 0; i < 4; i++) {
        int row = bm + ty * 4 + i;
#pragma unroll
        for (int j = 0; j < 4; j++) {
            int n = bn + tx * 4 + j;
            if (n < N) {
                int col = remap ? ((n == 0) ? 0 : n + 1) : n;
                Cz[(size_t)row * ldc + col] = c[i][j];
            }
        }
    }
}

// ---------------------------------------------------------------------------
// Causal conv (width 4) + SiLU -> g_xc2
// ---------------------------------------------------------------------------
__global__ void conv_silu_kernel(const float* __restrict__ cw,
                                 const float* __restrict__ cb)
{
    int i = blockIdx.x * blockDim.x + threadIdx.x;
    const int ngrp = DINNER / 4;
    if (i >= MROWS * ngrp) return;
    int m  = i / ngrp;
    int dg = i % ngrp;
    int l  = m % SEQLEN;
    int d0 = dg * 4;

    float4 acc = make_float4(cb[d0], cb[d0 + 1], cb[d0 + 2], cb[d0 + 3]);
#pragma unroll
    for (int t = 0; t < 4; t++) {
        int li = l - 3 + t;
        if (li >= 0) {
            const float4 v = *(const float4*)&g_xz[(size_t)(m - l + li) * (2 * DINNER) + d0];
            acc.x = fmaf(v.x, __ldg(&cw[(d0 + 0) * 4 + t]), acc.x);
            acc.y = fmaf(v.y, __ldg(&cw[(d0 + 1) * 4 + t]), acc.y);
            acc.z = fmaf(v.z, __ldg(&cw[(d0 + 2) * 4 + t]), acc.z);
            acc.w = fmaf(v.w, __ldg(&cw[(d0 + 3) * 4 + t]), acc.w);
        }
    }
    float4 o;
    o.x = acc.x / (1.f + expf(-acc.x));
    o.y = acc.y / (1.f + expf(-acc.y));
    o.z = acc.z / (1.f + expf(-acc.z));
    o.w = acc.w / (1.f + expf(-acc.w));
    ((float4*)g_xc2)[i] = o;
}

// ---------------------------------------------------------------------------
// Precompute {dt, dt*xc, D*xc*sz, sz}, TRANSPOSED to channel-major [ch][l].
// Warp = 32 consecutive channels; each thread owns 1 channel x 8 steps.
// Reads coalesced over d; writes 128B-contiguous per thread.
// ---------------------------------------------------------------------------
__global__ void pre_kernel_t(const float* __restrict__ dt_w,
                             const float* __restrict__ dt_b,
                             const float* __restrict__ Dp)
{
    const int NCB = BATCH * DINNER / 256;          // 12 channel-blocks
    int bid = blockIdx.x;                          // 1536 blocks
    int lgrp = bid / NCB;
    int cb   = bid % NCB;
    int ch = cb * 256 + threadIdx.x;
    int b = ch / DINNER, d = ch % DINNER;
    int l0 = lgrp * 8;

    float dw = __ldg(dt_w + d), db = __ldg(dt_b + d), Dv = __ldg(Dp + d);
    float4* outp = (float4*)g_pre + (size_t)ch * SEQLEN + l0;

#pragma unroll
    for (int j = 0; j < 8; j++) {
        int m = b * SEQLEN + l0 + j;
        float dtin = g_xdbl[(size_t)m * XDBL_LD];
        float xarg = fmaf(dtin, dw, db);
        float dt = fmaxf(xarg, 0.f) + log1pf(expf(-fabsf(xarg)));
        float xc = g_xc2[(size_t)m * DINNER + d];
        float z  = g_xz[(size_t)m * (2 * DINNER) + DINNER + d];
        float sz = z / (1.f + expf(-z));
        outp[j] = make_float4(dt, dt * xc, Dv * xc * sz, sz);
    }
}

// ---------------------------------------------------------------------------
// Selective scan: warp per channel; ch-major pre stream, 4-deep prefetch ring,
// 4 steps unrolled with interleaved shfl reduction trees; interleaved bf16
// y output ([hi,lo,hi] at 3d -> 1 sector per step).
// ---------------------------------------------------------------------------
__device__ __forceinline__ float fast_ex2(float x) {
    float r;
    asm("ex2.approx.ftz.f32 %0, %1;" : "=f"(r) : "f"(x));
    return r;
}

__global__ __launch_bounds__(256) void scan_kernel(const float* __restrict__ A_log)
{
    const int warp = threadIdx.x >> 5;
    const int lane = threadIdx.x & 31;
    const int ch = blockIdx.x * 8 + warp;
    const int b = ch / DINNER;
    const int d = ch % DINNER;
    const int n0 = 2 * lane;

    const float LOG2E = 1.4426950408889634f;
    const float An0 = -expf(A_log[n0])     * LOG2E;
    const float An1 = -expf(A_log[n0 + 1]) * LOG2E;

    const float4* prp = (const float4*)g_pre + (size_t)ch * SEQLEN;
    const float*  xb  = g_xdbl + (size_t)(b * SEQLEN) * XDBL_LD;
    __nv_bfloat16* yo = g_y2 + (size_t)(b * SEQLEN) * KP3 + 3 * d;

    float4 prb[4]; float2 Bb[4], Cb[4];
#pragma unroll
    for (int s = 0; s < 4; s++) {
        prb[s] = __ldg(prp + s);
        Bb[s] = __ldg((const float2*)(xb + (size_t)s * XDBL_LD + 2  + n0));
        Cb[s] = __ldg((const float2*)(xb + (size_t)s * XDBL_LD + 66 + n0));
    }

    float h0 = 0.f, h1 = 0.f;

    for (int l = 0; l < SEQLEN; l += 4) {
        float ya[4], pz[4], pw[4];
#pragma unroll
        for (int s = 0; s < 4; s++) {
            float4 pr = prb[s]; float2 Bv = Bb[s], Cv = Cb[s];
            float dA0 = fast_ex2(pr.x * An0);
            float dA1 = fast_ex2(pr.x * An1);
            h0 = fmaf(h0, dA0, Bv.x * pr.y);
            h1 = fmaf(h1, dA1, Bv.y * pr.y);
            ya[s] = fmaf(h0, Cv.x, h1 * Cv.y);
            pz[s] = pr.z; pw[s] = pr.w;
            int ln = l + 4 + s;
            if (ln > SEQLEN - 1) ln = SEQLEN - 1;
            prb[s] = __ldg(prp + ln);
            Bb[s] = __ldg((const float2*)(xb + (size_t)ln * XDBL_LD + 2  + n0));
            Cb[s] = __ldg((const float2*)(xb + (size_t)ln * XDBL_LD + 66 + n0));
        }
#pragma unroll
        for (int o = 16; o > 0; o >>= 1) {
            ya[0] += __shfl_xor_sync(0xffffffffu, ya[0], o);
            ya[1] += __shfl_xor_sync(0xffffffffu, ya[1], o);
            ya[2] += __shfl_xor_sync(0xffffffffu, ya[2], o);
            ya[3] += __shfl_xor_sync(0xffffffffu, ya[3], o);
        }
        if (lane == 0) {
#pragma unroll
            for (int s = 0; s < 4; s++) {
                float yv = fmaf(ya[s], pw[s], pz[s]);
                __nv_bfloat16 hi = __float2bfloat16_rn(yv);
                __nv_bfloat16 lo = __float2bfloat16_rn(yv - __bfloat162float(hi));
                __nv_bfloat16* p = yo + (size_t)(l + s) * KP3;
                p[0] = hi; p[1] = lo; p[2] = hi;
            }
        }
    }
}

// ---------------------------------------------------------------------------
extern "C" void kernel_launch(void* const* d_in, const int* in_sizes, int n_in,
                              void* d_out, int out_size)
{
    const float* x      = (const float*)d_in[0];
    const float* W_in   = (const float*)d_in[1];
    const float* conv_w = (const float*)d_in[2];
    const float* conv_b = (const float*)d_in[3];
    const float* W_x    = (const float*)d_in[4];
    const float* dt_w   = (const float*)d_in[5];
    const float* dt_b   = (const float*)d_in[6];
    const float* A_log  = (const float*)d_in[7];
    const float* D_par  = (const float*)d_in[8];
    const float* W_out  = (const float*)d_in[9];
    float* out = (float*)d_out;

    float *p_xz, *p_xc2, *p_xdbl, *p_part64, *p_pre;
    __nv_bfloat16 *p_xp, *p_wip, *p_y2, *p_wop;
    cudaGetSymbolAddress((void**)&p_xz,     g_xz);
    cudaGetSymbolAddress((void**)&p_xc2,    g_xc2);
    cudaGetSymbolAddress((void**)&p_xdbl,   g_xdbl);
    cudaGetSymbolAddress((void**)&p_part64, g_xconv);
    cudaGetSymbolAddress((void**)&p_pre,    g_pre);
    cudaGetSymbolAddress((void**)&p_xp,     g_xp);
    cudaGetSymbolAddress((void**)&p_wip,    g_wip);
    cudaGetSymbolAddress((void**)&p_y2,     g_y2);
    cudaGetSymbolAddress((void**)&p_wop,    g_wop);

    // 0) split-pack x, W_in (block layout), W_out (interleaved layout)
    {
        int t;
        t = MROWS * DMODEL / 4;
        split_pack<<<(t + 255) / 256, 256>>>(x, p_xp, t, DMODEL / 4, 0);
        t = 2 * DINNER * DMODEL / 4;
        split_pack<<<(t + 255) / 256, 256>>>(W_in, p_wip, t, DMODEL / 4, 1);
        t = DMODEL * DINNER / 4;
        split_pack<<<(t + 255) / 256, 256>>>(W_out, p_wop, t, DINNER / 4, 2);
    }

    // 1) xz = x @ W_in^T : [2048,3072]
    gemm_bf16p<<<dim3(2 * DINNER / 128, MROWS / 128, 1), 256>>>(
        p_xp, p_wip, p_xz, MROWS, 2 * DINNER, KP1, KP1);

    // 2) causal conv + silu
    {
        int total = MROWS * (DINNER / 4);
        conv_silu_kernel<<<(total + 255) / 256, 256>>>(conv_w, conv_b);
    }

    // 3) x_dbl = x_conv @ W_x^T (split-K=4 partials -> add)
    sgemm64<<<dim3((129 + 63) / 64, MROWS / 64, 4), 256>>>(
        p_xc2, W_x, p_part64, MROWS, 129, DINNER, XDBL_LD, 1, DINNER / 4);
    {
        int t4 = MROWS * XDBL_LD / 4;
        addk_kernel<<<(t4 + 255) / 256, 256>>>(p_part64, p_xdbl, t4, 4);
    }

    // 4) pre (channel-major transposed)
    pre_kernel_t<<<(BATCH * DINNER / 256) * (SEQLEN / 8), 256>>>(dt_w, dt_b, D_par);

    // 5) selective scan -> g_y2 (interleaved packed bf16)
    scan_kernel<<<(BATCH * DINNER) / 8, 256>>>(A_log);

    // 6) out = y @ W_out^T (split-K=4 partials in g_pre -> add)
    gemm_bf16p<<<dim3(DMODEL / 128, MROWS / 128, 4), 256>>>(
        p_y2, p_wop, p_pre, MROWS, DMODEL, KP3, KP3 / 4);
    {
        int t4 = MROWS * DMODEL / 4;
        addk_kernel<<<(t4 + 255) / 256, 256>>>(p_pre, out, t4, 4);
    }
}

// round 6
// speedup vs baseline: 1.5576x; 1.0096x over previous
#include <cuda_runtime.h>
#include <cuda_bf16.h>
#include <math.h>

#define BATCH   2
#define SEQLEN  1024
#define DMODEL  768
#define DINNER  1536
#define DSTATE  64
#define MROWS   (BATCH * SEQLEN)
#define XDBL_LD 132

#define KP1 (3 * DMODEL)             // 2304  (GEMM1 packed K, 3-block layout)
#define KP4 (4 * DINNER)             // 6144  (GEMM3 packed K, 4-wide interleaved)

// Scratch
__device__ float g_xz   [MROWS * 2 * DINNER];
__device__ float g_xconv[MROWS * DINNER];       // sgemm64 split-K partials
__device__ float g_xc2  [MROWS * DINNER];       // conv output
__device__ float g_xdbl [MROWS * XDBL_LD];
__device__ float g_pre  [MROWS * DINNER * 4];   // pre (ch-major) / GEMM3 partials
__device__ __nv_bfloat16 g_xp [MROWS * KP1];
__device__ __nv_bfloat16 g_wip[2 * DINNER * KP1];
__device__ __nv_bfloat16 g_y2 [MROWS * KP4];    // y packed [hi,lo,hi,0] per d
__device__ __nv_bfloat16 g_wop[DMODEL * KP4];   // W_out packed [hi,hi,lo,0] per d

// ---------------------------------------------------------------------------
// Split-pack fp32 [R,K] -> bf16.
// mode0: [R,3K] blocks [hi|lo|hi]; mode1: [R,3K] blocks [hi|hi|lo];
// mode2: [R,4K] interleaved per element [hi,hi,lo,0].
// ---------------------------------------------------------------------------
__global__ void split_pack(const float* __restrict__ in,
                           __nv_bfloat16* __restrict__ out,
                           int total4, int K4, int mode)
{
    int i = blockIdx.x * blockDim.x + threadIdx.x;
    if (i >= total4) return;
    int K = K4 * 4;
    int row = i / K4;
    int c4  = (i - row * K4) * 4;

    float4 v = *(const float4*)(in + (size_t)row * K + c4);
    float f[4] = {v.x, v.y, v.z, v.w};
    unsigned long long hs[4], ls[4];
#pragma unroll
    for (int t = 0; t < 4; t++) {
        __nv_bfloat16 h = __float2bfloat16_rn(f[t]);
        __nv_bfloat16 l = __float2bfloat16_rn(f[t] - __bfloat162float(h));
        hs[t] = (unsigned long long)__bfloat16_as_ushort(h);
        ls[t] = (unsigned long long)__bfloat16_as_ushort(l);
    }

    if (mode == 2) {
        // per element k -> [hi,hi,lo,0] as one u64; 4 elems = 32B contiguous
        unsigned long long* wp =
            (unsigned long long*)(out + (size_t)row * 4 * K + 4 * c4);
#pragma unroll
        for (int t = 0; t < 4; t++)
            wp[t] = hs[t] | (hs[t] << 16) | (ls[t] << 32);
    } else {
        unsigned h0 = (unsigned)hs[0] | ((unsigned)hs[1] << 16);
        unsigned h1 = (unsigned)hs[2] | ((unsigned)hs[3] << 16);
        unsigned l0 = (unsigned)ls[0] | ((unsigned)ls[1] << 16);
        unsigned l1 = (unsigned)ls[2] | ((unsigned)ls[3] << 16);
        uint2 hi = make_uint2(h0, h1);
        uint2 lo = make_uint2(l0, l1);
        __nv_bfloat16* base = out + (size_t)row * 3 * K + c4;
        *(uint2*)(base)         = hi;
        *(uint2*)(base + K)     = mode ? hi : lo;
        *(uint2*)(base + 2 * K) = mode ? lo : hi;
    }
}

// ---------------------------------------------------------------------------
// 3-stage pipelined bf16 tensor GEMM, 128x128x32, launch_bounds(256,2).
// gridDim.z = split-K slices (slice z: kBase=z*kLen, writes C+z*M*N).
// ---------------------------------------------------------------------------
__device__ __forceinline__ void mma16816(float* c, const unsigned* a,
                                         const unsigned* b)
{
    asm volatile(
        "mma.sync.aligned.m16n8k16.row.col.f32.bf16.bf16.f32 "
        "{%0,%1,%2,%3}, {%4,%5,%6,%7}, {%8,%9}, {%0,%1,%2,%3};\n"
        : "+f"(c[0]), "+f"(c[1]), "+f"(c[2]), "+f"(c[3])
        : "r"(a[0]), "r"(a[1]), "r"(a[2]), "r"(a[3]),
          "r"(b[0]), "r"(b[1]));
}

__device__ __forceinline__ void ldsm4(unsigned& r0, unsigned& r1,
                                      unsigned& r2, unsigned& r3,
                                      const void* p)
{
    unsigned a = (unsigned)__cvta_generic_to_shared(p);
    asm volatile("ldmatrix.sync.aligned.m8n8.x4.shared.b16 {%0,%1,%2,%3}, [%4];"
                 : "=r"(r0), "=r"(r1), "=r"(r2), "=r"(r3) : "r"(a));
}

__device__ __forceinline__ void cp16(void* smem, const void* gmem)
{
    unsigned s = (unsigned)__cvta_generic_to_shared(smem);
    asm volatile("cp.async.cg.shared.global [%0], [%1], 16;" :: "r"(s), "l"(gmem));
}

#define NSTAGE 3

__global__ __launch_bounds__(256, 2) void gemm_bf16p(
    const __nv_bfloat16* __restrict__ A, const __nv_bfloat16* __restrict__ B,
    float* __restrict__ C, int M, int N, int K, int kLen)
{
    constexpr int BM = 128, BN = 128, BK = 32;
    constexpr int MT = 4, NT = 4;

    __shared__ __nv_bfloat16 As[NSTAGE][BM][40];
    __shared__ __nv_bfloat16 Bs[NSTAGE][BN][40];

    const int tid  = threadIdx.x;
    const int lane = tid & 31;
    const int wid  = tid >> 5;
    const int wm   = wid & 1;
    const int wn   = wid >> 1;
    const int bm   = blockIdx.y * BM;
    const int bn   = blockIdx.x * BN;
    const int kBase = blockIdx.z * kLen;
    float* Cz = C + (size_t)blockIdx.z * M * N;

    const int srow = tid >> 2;
    const int sseg = tid & 3;
    const __nv_bfloat16* Ag = A + (size_t)(bm + srow) * K + kBase + sseg * 8;
    const __nv_bfloat16* Bg = B + (size_t)(bn + srow) * K + kBase + sseg * 8;

    float c[MT][NT][4];
#pragma unroll
    for (int i = 0; i < MT; i++)
#pragma unroll
        for (int j = 0; j < NT; j++)
#pragma unroll
            for (int r = 0; r < 4; r++) c[i][j][r] = 0.f;

    auto load_stage = [&](int s, int k0) {
        cp16(&As[s][srow][sseg * 8],      Ag + k0);
        cp16(&As[s][srow + 64][sseg * 8], Ag + (size_t)64 * K + k0);
        cp16(&Bs[s][srow][sseg * 8],      Bg + k0);
        cp16(&Bs[s][srow + 64][sseg * 8], Bg + (size_t)64 * K + k0);
    };

    auto compute_half = [&](int s, int ks) {
        unsigned a[MT][4], b[NT][2];
#pragma unroll
        for (int i = 0; i < MT; i++)
            ldsm4(a[i][0], a[i][1], a[i][2], a[i][3],
                  &As[s][wm * 64 + i * 16 + (lane & 15)]
                       [ks * 16 + ((lane >> 4) << 3)]);
#pragma unroll
        for (int j2 = 0; j2 < NT / 2; j2++) {
            int r = wn * 32 + j2 * 16 + ((lane >> 4) << 3) + (lane & 7);
            int cb = (((lane >> 3) & 1) << 3) + ks * 16;
            ldsm4(b[2 * j2][0], b[2 * j2][1], b[2 * j2 + 1][0], b[2 * j2 + 1][1],
                  &Bs[s][r][cb]);
        }
#pragma unroll
        for (int i = 0; i < MT; i++)
#pragma unroll
            for (int j = 0; j < NT; j++)
                mma16816(c[i][j], a[i], b[j]);
    };

    const int nIter = kLen / BK;

    load_stage(0, 0);
    asm volatile("cp.async.commit_group;");
    if (1 < nIter) load_stage(1, BK);
    asm volatile("cp.async.commit_group;");
    asm volatile("cp.async.wait_group 1;");
    __syncthreads();

    int s = 0;
    for (int it = 0; it < nIter; it++) {
        compute_half(s, 0);
        {
            int nf = it + 2;
            int sl = s + 2; if (sl >= NSTAGE) sl -= NSTAGE;
            if (nf < nIter) load_stage(sl, nf * BK);
            asm volatile("cp.async.commit_group;");
        }
        compute_half(s, 1);
        asm volatile("cp.async.wait_group 1;");
        __syncthreads();
        s = (s + 1 == NSTAGE) ? 0 : s + 1;
    }

#pragma unroll
    for (int i = 0; i < MT; i++) {
        int row = bm + wm * 64 + i * 16 + (lane >> 2);
#pragma unroll
        for (int j = 0; j < NT; j++) {
            int col = bn + wn * 32 + j * 8 + (lane & 3) * 2;
            *(float2*)(Cz + (size_t)row * N + col) =
                make_float2(c[i][j][0], c[i][j][1]);
            *(float2*)(Cz + (size_t)(row + 8) * N + col) =
                make_float2(c[i][j][2], c[i][j][3]);
        }
    }
}

// Split-K reduction
__global__ void addk_kernel(const float* __restrict__ p, float* __restrict__ out,
                            int total4, int ns)
{
    int i = blockIdx.x * blockDim.x + threadIdx.x;
    if (i >= total4) return;
    float4 a = ((const float4*)p)[i];
    for (int s = 1; s < ns; s++) {
        float4 b = ((const float4*)p)[i + (size_t)s * total4];
        a.x += b.x; a.y += b.y; a.z += b.z; a.w += b.w;
    }
    ((float4*)out)[i] = a;
}

// ---------------------------------------------------------------------------
// SGEMM 64x64x16, fp32, N bounds + remap; split-K via gridDim.z.
// ---------------------------------------------------------------------------
__global__ __launch_bounds__(256) void sgemm64(
    const float* __restrict__ A, const float* __restrict__ B,
    float* __restrict__ C, int M, int N, int K, int ldc, int remap, int kLen)
{
    __shared__ float As[16][68];
    __shared__ float Bs[16][68];

    const int tid = threadIdx.x;
    const int bm = blockIdx.y * 64;
    const int bn = blockIdx.x * 64;
    const int kBase = blockIdx.z * kLen;
    float* Cz = C + (size_t)blockIdx.z * M * ldc;

    const int lr = tid >> 2;
    const int lk = (tid & 3) * 4;
    const int tx = tid & 15, ty = tid >> 4;

    float c[4][4];
#pragma unroll
    for (int i = 0; i < 4; i++)
#pragma unroll
        for (int j = 0; j < 4; j++) c[i][j] = 0.f;

    const float* Ag = A + (size_t)(bm + lr) * K + kBase + lk;
    const int brow = bn + lr;
    const float* Bg = B + (size_t)brow * K + kBase + lk;
    const bool bok = (brow < N);

    for (int k0 = 0; k0 < kLen; k0 += 16) {
        float4 av = *(const float4*)(Ag + k0);
        float4 bv = bok ? *(const float4*)(Bg + k0)
                        : make_float4(0.f, 0.f, 0.f, 0.f);
        As[lk + 0][lr] = av.x; As[lk + 1][lr] = av.y;
        As[lk + 2][lr] = av.z; As[lk + 3][lr] = av.w;
        Bs[lk + 0][lr] = bv.x; Bs[lk + 1][lr] = bv.y;
        Bs[lk + 2][lr] = bv.z; Bs[lk + 3][lr] = bv.w;
        __syncthreads();

#pragma unroll
        for (int k = 0; k < 16; k++) {
            float4 a = *(const float4*)&As[k][ty * 4];
            float4 b = *(const float4*)&Bs[k][tx * 4];
            float ar[4] = {a.x, a.y, a.z, a.w};
            float br[4] = {b.x, b.y, b.z, b.w};
#pragma unroll
            for (int i = 0; i < 4; i++)
#pragma unroll
                for (int j = 0; j < 4; j++)
                    c[i][j] = fmaf(ar[i], br[j], c[i][j]);
        }
        __syncthreads();
    }

#pragma unroll
    for (int i = 0; i < 4; i++) {
        int row = bm + ty * 4 + i;
#pragma unroll
        for (int j = 0; j < 4; j++) {
            int n = bn + tx * 4 + j;
            if (n < N) {
                int col = remap ? ((n == 0) ? 0 : n + 1) : n;
                Cz[(size_t)row * ldc + col] = c[i][j];
            }
        }
    }
}

// ---------------------------------------------------------------------------
// Causal conv (width 4) + SiLU -> g_xc2
// ---------------------------------------------------------------------------
__global__ void conv_silu_kernel(const float* __restrict__ cw,
                                 const float* __restrict__ cb)
{
    int i = blockIdx.x * blockDim.x + threadIdx.x;
    const int ngrp = DINNER / 4;
    if (i >= MROWS * ngrp) return;
    int m  = i / ngrp;
    int dg = i % ngrp;
    int l  = m % SEQLEN;
    int d0 = dg * 4;

    float4 acc = make_float4(cb[d0], cb[d0 + 1], cb[d0 + 2], cb[d0 + 3]);
#pragma unroll
    for (int t = 0; t < 4; t++) {
        int li = l - 3 + t;
        if (li >= 0) {
            const float4 v = *(const float4*)&g_xz[(size_t)(m - l + li) * (2 * DINNER) + d0];
            acc.x = fmaf(v.x, __ldg(&cw[(d0 + 0) * 4 + t]), acc.x);
            acc.y = fmaf(v.y, __ldg(&cw[(d0 + 1) * 4 + t]), acc.y);
            acc.z = fmaf(v.z, __ldg(&cw[(d0 + 2) * 4 + t]), acc.z);
            acc.w = fmaf(v.w, __ldg(&cw[(d0 + 3) * 4 + t]), acc.w);
        }
    }
    float4 o;
    o.x = acc.x / (1.f + expf(-acc.x));
    o.y = acc.y / (1.f + expf(-acc.y));
    o.z = acc.z / (1.f + expf(-acc.z));
    o.w = acc.w / (1.f + expf(-acc.w));
    ((float4*)g_xc2)[i] = o;
}

// ---------------------------------------------------------------------------
// Precompute {dt, dt*xc, D*xc*sz, sz}, channel-major [ch][l].
// ---------------------------------------------------------------------------
__global__ void pre_kernel_t(const float* __restrict__ dt_w,
                             const float* __restrict__ dt_b,
                             const float* __restrict__ Dp)
{
    const int NCB = BATCH * DINNER / 256;
    int bid = blockIdx.x;
    int lgrp = bid / NCB;
    int cb   = bid % NCB;
    int ch = cb * 256 + threadIdx.x;
    int b = ch / DINNER, d = ch % DINNER;
    int l0 = lgrp * 8;

    float dw = __ldg(dt_w + d), db = __ldg(dt_b + d), Dv = __ldg(Dp + d);
    float4* outp = (float4*)g_pre + (size_t)ch * SEQLEN + l0;

#pragma unroll
    for (int j = 0; j < 8; j++) {
        int m = b * SEQLEN + l0 + j;
        float dtin = g_xdbl[(size_t)m * XDBL_LD];
        float xarg = fmaf(dtin, dw, db);
        float dt = fmaxf(xarg, 0.f) + log1pf(expf(-fabsf(xarg)));
        float xc = g_xc2[(size_t)m * DINNER + d];
        float z  = g_xz[(size_t)m * (2 * DINNER) + DINNER + d];
        float sz = z / (1.f + expf(-z));
        outp[j] = make_float4(dt, dt * xc, Dv * xc * sz, sz);
    }
}

// ---------------------------------------------------------------------------
// Selective scan: warp per channel; unroll x8, 8-slot prefetch ring,
// 8 interleaved shfl trees, ONE STG.64 (lanes 0-7) per 8 steps.
// ---------------------------------------------------------------------------
__device__ __forceinline__ float fast_ex2(float x) {
    float r;
    asm("ex2.approx.ftz.f32 %0, %1;" : "=f"(r) : "f"(x));
    return r;
}

__global__ __launch_bounds__(256) void scan_kernel(const float* __restrict__ A_log)
{
    const int warp = threadIdx.x >> 5;
    const int lane = threadIdx.x & 31;
    const int ch = blockIdx.x * 8 + warp;
    const int b = ch / DINNER;
    const int d = ch % DINNER;
    const int n0 = 2 * lane;

    const float LOG2E = 1.4426950408889634f;
    const float An0 = -expf(A_log[n0])     * LOG2E;
    const float An1 = -expf(A_log[n0 + 1]) * LOG2E;

    const float4* prp = (const float4*)g_pre + (size_t)ch * SEQLEN;
    const float*  xb  = g_xdbl + (size_t)(b * SEQLEN) * XDBL_LD;
    unsigned long long* yo =
        (unsigned long long*)(g_y2 + (size_t)(b * SEQLEN) * KP4) + d;
    const int ystride = KP4 / 4;   // u64 elements per timestep row

    float4 prb[8]; float2 Bb[8], Cb[8];
#pragma unroll
    for (int s = 0; s < 8; s++) {
        prb[s] = __ldg(prp + s);
        Bb[s] = __ldg((const float2*)(xb + (size_t)s * XDBL_LD + 2  + n0));
        Cb[s] = __ldg((const float2*)(xb + (size_t)s * XDBL_LD + 66 + n0));
    }

    float h0 = 0.f, h1 = 0.f;

    for (int l = 0; l < SEQLEN; l += 8) {
        float ya[8], pz[8], pw[8];
#pragma unroll
        for (int s = 0; s < 8; s++) {
            float4 pr = prb[s]; float2 Bv = Bb[s], Cv = Cb[s];
            float dA0 = fast_ex2(pr.x * An0);
            float dA1 = fast_ex2(pr.x * An1);
            h0 = fmaf(h0, dA0, Bv.x * pr.y);
            h1 = fmaf(h1, dA1, Bv.y * pr.y);
            ya[s] = fmaf(h0, Cv.x, h1 * Cv.y);
            pz[s] = pr.z; pw[s] = pr.w;
            int ln = l + 8 + s;
            if (ln > SEQLEN - 1) ln = SEQLEN - 1;
            prb[s] = __ldg(prp + ln);
            Bb[s] = __ldg((const float2*)(xb + (size_t)ln * XDBL_LD + 2  + n0));
            Cb[s] = __ldg((const float2*)(xb + (size_t)ln * XDBL_LD + 66 + n0));
        }
#pragma unroll
        for (int o = 16; o > 0; o >>= 1) {
#pragma unroll
            for (int s = 0; s < 8; s++)
                ya[s] += __shfl_xor_sync(0xffffffffu, ya[s], o);
        }
        // lane s (0..7) takes slot s via SEL chain, one STG.64 for 8 steps
        float sy = ya[0], sz_ = pz[0], sw = pw[0];
#pragma unroll
        for (int s = 1; s < 8; s++) {
            bool mk = (lane == s);
            sy = mk ? ya[s] : sy;
            sz_ = mk ? pz[s] : sz_;
            sw = mk ? pw[s] : sw;
        }
        if (lane < 8) {
            float yv = fmaf(sy, sw, sz_);
            __nv_bfloat16 hi = __float2bfloat16_rn(yv);
            __nv_bfloat16 lo = __float2bfloat16_rn(yv - __bfloat162float(hi));
            unsigned long long hb = (unsigned long long)__bfloat16_as_ushort(hi);
            unsigned long long lb = (unsigned long long)__bfloat16_as_ushort(lo);
            yo[(size_t)(l + lane) * ystride] = hb | (lb << 16) | (hb << 32);
        }
    }
}

// ---------------------------------------------------------------------------
extern "C" void kernel_launch(void* const* d_in, const int* in_sizes, int n_in,
                              void* d_out, int out_size)
{
    const float* x      = (const float*)d_in[0];
    const float* W_in   = (const float*)d_in[1];
    const float* conv_w = (const float*)d_in[2];
    const float* conv_b = (const float*)d_in[3];
    const float* W_x    = (const float*)d_in[4];
    const float* dt_w   = (const float*)d_in[5];
    const float* dt_b   = (const float*)d_in[6];
    const float* A_log  = (const float*)d_in[7];
    const float* D_par  = (const float*)d_in[8];
    const float* W_out  = (const float*)d_in[9];
    float* out = (float*)d_out;

    float *p_xz, *p_xc2, *p_xdbl, *p_part64, *p_pre;
    __nv_bfloat16 *p_xp, *p_wip, *p_y2, *p_wop;
    cudaGetSymbolAddress((void**)&p_xz,     g_xz);
    cudaGetSymbolAddress((void**)&p_xc2,    g_xc2);
    cudaGetSymbolAddress((void**)&p_xdbl,   g_xdbl);
    cudaGetSymbolAddress((void**)&p_part64, g_xconv);
    cudaGetSymbolAddress((void**)&p_pre,    g_pre);
    cudaGetSymbolAddress((void**)&p_xp,     g_xp);
    cudaGetSymbolAddress((void**)&p_wip,    g_wip);
    cudaGetSymbolAddress((void**)&p_y2,     g_y2);
    cudaGetSymbolAddress((void**)&p_wop,    g_wop);

    // 0) split-pack x, W_in (block), W_out (4-wide interleaved)
    {
        int t;
        t = MROWS * DMODEL / 4;
        split_pack<<<(t + 255) / 256, 256>>>(x, p_xp, t, DMODEL / 4, 0);
        t = 2 * DINNER * DMODEL / 4;
        split_pack<<<(t + 255) / 256, 256>>>(W_in, p_wip, t, DMODEL / 4, 1);
        t = DMODEL * DINNER / 4;
        split_pack<<<(t + 255) / 256, 256>>>(W_out, p_wop, t, DINNER / 4, 2);
    }

    // 1) xz = x @ W_in^T
    gemm_bf16p<<<dim3(2 * DINNER / 128, MROWS / 128, 1), 256>>>(
        p_xp, p_wip, p_xz, MROWS, 2 * DINNER, KP1, KP1);

    // 2) causal conv + silu
    {
        int total = MROWS * (DINNER / 4);
        conv_silu_kernel<<<(total + 255) / 256, 256>>>(conv_w, conv_b);
    }

    // 3) x_dbl = x_conv @ W_x^T (split-K=4 -> add)
    sgemm64<<<dim3((129 + 63) / 64, MROWS / 64, 4), 256>>>(
        p_xc2, W_x, p_part64, MROWS, 129, DINNER, XDBL_LD, 1, DINNER / 4);
    {
        int t4 = MROWS * XDBL_LD / 4;
        addk_kernel<<<(t4 + 255) / 256, 256>>>(p_part64, p_xdbl, t4, 4);
    }

    // 4) pre (channel-major)
    pre_kernel_t<<<(BATCH * DINNER / 256) * (SEQLEN / 8), 256>>>(dt_w, dt_b, D_par);

    // 5) selective scan -> g_y2 (4-wide packed bf16)
    scan_kernel<<<(BATCH * DINNER) / 8, 256>>>(A_log);

    // 6) out = y @ W_out^T (K=6144, split-K=4 in g_pre -> add)
    gemm_bf16p<<<dim3(DMODEL / 128, MROWS / 128, 4), 256>>>(
        p_y2, p_wop, p_pre, MROWS, DMODEL, KP4, KP4 / 4);
    {
        int t4 = MROWS * DMODEL / 4;
        addk_kernel<<<(t4 + 255) / 256, 256>>>(p_pre, out, t4, 4);
    }
}